// round 17
// baseline (speedup 1.0000x reference)
#include <cuda_runtime.h>
#include <stdint.h>
#include <math.h>

#define H 64
#define WARPS 8
#define BATCH 2
#define RPB (WARPS * BATCH)
#define THREADS (WARPS * 32)
#define MAXPART 1024

__device__ float2 g_part[MAXPART];
__device__ unsigned int g_done = 0;

typedef unsigned long long u64;

__device__ __forceinline__ u64 addf32x2(u64 a, u64 b)
{
    u64 r;
    asm("add.rn.f32x2 %0, %1, %2;" : "=l"(r) : "l"(a), "l"(b));
    return r;
}
__device__ __forceinline__ u64 pk(float lo, float hi)
{
    u64 r;
    asm("mov.b64 %0, {%1, %2};" : "=l"(r) : "f"(lo), "f"(hi));
    return r;
}
__device__ __forceinline__ void upk(u64 v, float& lo, float& hi)
{
    asm("mov.b64 {%0, %1}, %2;" : "=f"(lo), "=f"(hi) : "l"(v));
}

__device__ __forceinline__ void tail(float dr, float u, float& acc, float& cnt)
{
    const float vv = __uint_as_float(__float_as_uint(u) ^ (__float_as_uint(dr) & 0x80000000u));
    const float t  = fmaxf(vv + 1.0f, 0.0f);          // finite even for NaN dr
    const float wt = __saturatef(fabsf(dr));          // 0 on tie/invalid(NaN), 1 otherwise
    acc = fmaf(t, wt, acc);
    cnt += wt;
}

__global__ void __launch_bounds__(THREADS, 6) pairloss_kernel(
    const float* __restrict__ scores,
    const int* __restrict__ rankings,
    const uint8_t* __restrict__ mask,
    float* __restrict__ out,
    int B, int nblocks)
{
    __shared__ ulonglong2 sh[WARPS][48];
    __shared__ float2 sh_row[RPB];
    __shared__ int s_last;

    const int lane = threadIdx.x & 31;
    const int w    = threadIdx.x >> 5;
    const int rA   = blockIdx.x * RPB + w * BATCH;   // this warp's first row

    const float NaNf = __int_as_float(0x7fffffff);

    // prefetch batch 0 raw inputs
    int base = rA * H + 2 * lane;
    float2 sc = *reinterpret_cast<const float2*>(scores + base);
    int2   rk = *reinterpret_cast<const int2*>(rankings + base);
    uchar2 mk = *reinterpret_cast<const uchar2*>(mask + base);

    #pragma unroll
    for (int b = 0; b < BATCH; ++b) {
        // prefetch NEXT row's raw inputs BEFORE computing this row (hides LDG latency)
        float2 sc_n; int2 rk_n; uchar2 mk_n;
        if (b + 1 < BATCH) {
            const int nb = base + H;
            sc_n = *reinterpret_cast<const float2*>(scores + nb);
            rk_n = *reinterpret_cast<const int2*>(rankings + nb);
            mk_n = *reinterpret_cast<const uchar2*>(mask + nb);
        }

        const float s0 = sc.x, s1 = sc.y;
        const bool  v0 = (mk.x != 0) && (rk.x > 0);
        const bool  v1 = (mk.y != 0) && (rk.y > 0);
        const float fr0 = v0 ? (float)rk.x : NaNf;   // invalid -> NaN rank: gates its pairs to 0
        const float fr1 = v1 ? (float)rk.y : NaNf;

        __syncwarp();                                // b>0: all lanes done reading old tile
        const ulonglong2 mine = make_ulonglong2(pk(fr0, fr1), pk(s0, s1));
        sh[w][lane] = mine;
        if (lane < 16) sh[w][lane + 32] = mine;      // duplicate for wrap-free indexing
        __syncwarp();

        const u64 nr0 = pk(-fr0, -fr0);              // -NaN is still NaN
        const u64 nr1 = pk(-fr1, -fr1);
        const u64 ns0 = pk(-s0, -s0);
        const u64 ns1 = pk(-s1, -s1);

        float accA = 0.f, cntA = 0.f, accB = 0.f, cntB = 0.f;

        // intra-group pair {2*lane, 2*lane+1}
        tail(fr1 - fr0, s1 - s0, accA, cntA);

        const ulonglong2* p = &sh[w][lane];

        #pragma unroll
        for (int k = 1; k <= 15; ++k) {
            const ulonglong2 q = p[k];               // partner group (lane+k) mod 32
            const u64 dra = addf32x2(q.x, nr0);
            const u64 drb = addf32x2(q.x, nr1);
            const u64 ua  = addf32x2(q.y, ns0);
            const u64 ub  = addf32x2(q.y, ns1);
            float d0, d1, d2, d3, x0, x1, x2, x3;
            upk(dra, d0, d1); upk(drb, d2, d3);
            upk(ua,  x0, x1); upk(ub,  x2, x3);
            tail(d0, x0, accA, cntA);
            tail(d1, x1, accA, cntA);
            tail(d2, x2, accB, cntB);
            tail(d3, x3, accB, cntB);
        }

        // k = 16: only lanes 0..15 own these group pairs (avoid double count)
        {
            const ulonglong2 q = p[16];
            const u64 qr = (lane < 16) ? q.x : pk(NaNf, NaNf);   // NaN -> weight 0
            const u64 dra = addf32x2(qr, nr0);
            const u64 drb = addf32x2(qr, nr1);
            const u64 ua  = addf32x2(q.y, ns0);
            const u64 ub  = addf32x2(q.y, ns1);
            float d0, d1, d2, d3, x0, x1, x2, x3;
            upk(dra, d0, d1); upk(drb, d2, d3);
            upk(ua,  x0, x1); upk(ub,  x2, x3);
            tail(d0, x0, accA, cntA);
            tail(d1, x1, accA, cntA);
            tail(d2, x2, accB, cntB);
            tail(d3, x3, accB, cntB);
        }

        float acc = accA + accB;
        float cnt = cntA + cntB;
        #pragma unroll
        for (int o = 16; o > 0; o >>= 1) {
            acc += __shfl_down_sync(0xffffffffu, acc, o);
            cnt += __shfl_down_sync(0xffffffffu, cnt, o);
        }
        if (lane == 0) {
            sh_row[w * BATCH + b] =
                make_float2((cnt > 0.f) ? (acc / cnt) : 0.f, (cnt > 0.f) ? 1.f : 0.f);
        }

        // rotate prefetched raw into current
        sc = sc_n; rk = rk_n; mk = mk_n;
        base += H;
    }
    __syncthreads();

    if (threadIdx.x == 0) {
        float l = 0.f, h = 0.f;
        #pragma unroll
        for (int i = 0; i < RPB; ++i) { l += sh_row[i].x; h += sh_row[i].y; }
        g_part[blockIdx.x] = make_float2(l, h);
        __threadfence();
        const unsigned int t = atomicAdd(&g_done, 1u);
        s_last = (t == (unsigned int)(nblocks - 1)) ? 1 : 0;
    }
    __syncthreads();

    // last block reduces all partials in FIXED index order -> deterministic
    if (s_last) {
        __threadfence();
        float l = 0.f, h = 0.f;
        for (int i = threadIdx.x; i < nblocks; i += THREADS) {
            const float2 pp = g_part[i];
            l += pp.x;
            h += pp.y;
        }
        __shared__ float f_l[THREADS];
        __shared__ float f_h[THREADS];
        f_l[threadIdx.x] = l;
        f_h[threadIdx.x] = h;
        __syncthreads();
        #pragma unroll
        for (int s = THREADS / 2; s > 0; s >>= 1) {
            if (threadIdx.x < s) {
                f_l[threadIdx.x] += f_l[threadIdx.x + s];
                f_h[threadIdx.x] += f_h[threadIdx.x + s];
            }
            __syncthreads();
        }
        if (threadIdx.x == 0) {
            const float n = f_h[0];
            out[0] = (n > 0.f) ? (f_l[0] / n) : 0.f;
            g_done = 0;                      // reset for next graph replay
        }
    }
}

extern "C" void kernel_launch(void* const* d_in, const int* in_sizes, int n_in,
                              void* d_out, int out_size)
{
    const float*   scores   = (const float*)d_in[0];
    const int*     rankings = (const int*)d_in[1];
    const uint8_t* mask     = (const uint8_t*)d_in[2];
    float*         out      = (float*)d_out;

    const int B = in_sizes[0] / H;
    const int nblocks = (B + RPB - 1) / RPB;

    pairloss_kernel<<<nblocks, THREADS>>>(scores, rankings, mask, out, B, nblocks);
}